// round 14
// baseline (speedup 1.0000x reference)
#include <cuda_runtime.h>
#include <cuda_fp16.h>

// Problem constants
#define BB 2
#define HH 8
#define NN 1024
#define MM 1024
#define SS 4
#define CC 64
#define DM 512
#define SCALE 0.125f   // 1/sqrt(64)

// fp16 scratch (device globals: allocation-free)
__device__ __half qh_g[(size_t)BB*HH*NN*CC];   // [bh][n][c]
__device__ __half kh_g[(size_t)BB*HH*MM*CC];   // [bh][m][c]
__device__ __half vt_g[(size_t)BB*HH*CC*MM];   // [bh][c][m]  (transposed V)
__device__ __half xh_g[(size_t)3*BB*NN*DM];    // fp16 inputs  [which][row][d]
__device__ __half wh_g[(size_t)3*DM*DM];       // fp16 weights [which][j][d]

// ---------------------------------------------------------------- mma helpers
__device__ __forceinline__ unsigned smem_u32(const void* p) {
    return (unsigned)__cvta_generic_to_shared(p);
}

__device__ __forceinline__ void ldsm_x4(unsigned r[4], const __half* base,
                                        int row, int col, int ld, int lane) {
    const __half* p = base + (size_t)(row + (lane & 7) + ((lane >> 3) & 1) * 8) * ld
                           + col + (lane >> 4) * 8;
    unsigned a = smem_u32(p);
    asm volatile("ldmatrix.sync.aligned.m8n8.x4.shared.b16 {%0,%1,%2,%3},[%4];\n"
                 : "=r"(r[0]), "=r"(r[1]), "=r"(r[2]), "=r"(r[3]) : "r"(a));
}

// B-frag pair over two n-tiles (nrow, nrow+8), same kcol
__device__ __forceinline__ void ldsm_b_x4n(unsigned r[4], const __half* base,
                                           int nrow, int kcol, int ld, int lane) {
    const __half* p = base + (size_t)(nrow + (lane & 7) + ((lane >> 4) & 1) * 8) * ld
                           + kcol + ((lane >> 3) & 1) * 8;
    unsigned a = smem_u32(p);
    asm volatile("ldmatrix.sync.aligned.m8n8.x4.shared.b16 {%0,%1,%2,%3},[%4];\n"
                 : "=r"(r[0]), "=r"(r[1]), "=r"(r[2]), "=r"(r[3]) : "r"(a));
}

// B-frag pair over two k-tiles (kcol, kcol+16), same nrow
__device__ __forceinline__ void ldsm_b_x4k(unsigned r[4], const __half* base,
                                           int nrow, int kcol, int ld, int lane) {
    const __half* p = base + (size_t)(nrow + (lane & 7)) * ld
                           + kcol + ((lane >> 3) & 1) * 8 + ((lane >> 4) & 1) * 16;
    unsigned a = smem_u32(p);
    asm volatile("ldmatrix.sync.aligned.m8n8.x4.shared.b16 {%0,%1,%2,%3},[%4];\n"
                 : "=r"(r[0]), "=r"(r[1]), "=r"(r[2]), "=r"(r[3]) : "r"(a));
}

__device__ __forceinline__ void mma16816(float c[4], const unsigned a[4], const unsigned b[2]) {
    asm volatile("mma.sync.aligned.m16n8k16.row.col.f32.f16.f16.f32 "
                 "{%0,%1,%2,%3},{%4,%5,%6,%7},{%8,%9},{%0,%1,%2,%3};\n"
                 : "+f"(c[0]), "+f"(c[1]), "+f"(c[2]), "+f"(c[3])
                 : "r"(a[0]), "r"(a[1]), "r"(a[2]), "r"(a[3]), "r"(b[0]), "r"(b[1]));
}

// =====================================================================
// Kernel 0: convert X and W to fp16.
// =====================================================================
#define X4_PERX (BB * NN * DM / 4)
#define X4_PERW (DM * DM / 4)
#define X4_XTOT (3 * X4_PERX)
#define X4_TOT  (X4_XTOT + 3 * X4_PERW)

__global__ __launch_bounds__(256)
void convert_kernel(const float* __restrict__ Xq, const float* __restrict__ Xk,
                    const float* __restrict__ Xv, const float* __restrict__ Wq,
                    const float* __restrict__ Wk, const float* __restrict__ Wv) {
    int idx = blockIdx.x * 256 + threadIdx.x;
    if (idx >= X4_TOT) return;
    float4 v;
    __half* dst;
    if (idx < X4_XTOT) {
        int which = idx / X4_PERX, off = idx - which * X4_PERX;
        const float* src = (which == 0) ? Xq : (which == 1) ? Xk : Xv;
        v = __ldg(reinterpret_cast<const float4*>(src) + off);
        dst = xh_g + (size_t)which * (BB * NN * DM) + (size_t)off * 4;
    } else {
        int j = idx - X4_XTOT;
        int which = j / X4_PERW, off = j - which * X4_PERW;
        const float* src = (which == 0) ? Wq : (which == 1) ? Wk : Wv;
        v = __ldg(reinterpret_cast<const float4*>(src) + off);
        dst = wh_g + (size_t)which * (DM * DM) + (size_t)off * 4;
    }
    __half2* d2 = reinterpret_cast<__half2*>(dst);
    d2[0] = __floats2half2_rn(v.x, v.y);
    d2[1] = __floats2half2_rn(v.z, v.w);
}

// =====================================================================
// Kernel 1: projections from fp16, 128x128 tiles (TK=64), double-buffered.
// grid (16, 4, 3) = 192 CTAs = ONE full wave, 512 threads, 2 CTAs/SM.
// =====================================================================
__global__ __launch_bounds__(512, 2)
void proj_kernel(const float* __restrict__ bq, const float* __restrict__ bk,
                 const float* __restrict__ bv) {
    const int which = blockIdx.z;
    const __half* X = xh_g + (size_t)which * (BB * NN * DM);
    const __half* W = wh_g + (size_t)which * (DM * DM);
    const float* bias = (which == 0) ? bq : (which == 1) ? bk : bv;

    __shared__ __half As[2 * 128 * 72];   // 36864 B
    __shared__ __half Bs[2 * 128 * 72];   // 36864 B

    const int row0 = blockIdx.x * 128;
    const int j0 = blockIdx.y * 128;      // spans heads 2*by, 2*by+1
    const int tid = threadIdx.x;
    const int warp = tid >> 5, lane = tid & 31;
    const int wn = warp & 3, wc = warp >> 2;   // 4x4 warps, 32x32 per warp

    float acc[2][4][4] = {};
    uint4 ra[2], rb[2];

    // staging: 128 rows x 8 uint4 per matrix, 2/thread
    #pragma unroll
    for (int it = 0; it < 2; it++) {
        int idx = tid + it * 512;
        int r = idx >> 3, u = idx & 7;
        ra[it] = *reinterpret_cast<const uint4*>(X + (size_t)(row0 + r) * DM + u * 8);
        rb[it] = *reinterpret_cast<const uint4*>(W + (size_t)(j0 + r) * DM + u * 8);
    }

    for (int kc8 = 0; kc8 < 8; kc8++) {
        __half* Ab = As + (kc8 & 1) * 128 * 72;
        __half* Bb = Bs + (kc8 & 1) * 128 * 72;
        #pragma unroll
        for (int it = 0; it < 2; it++) {
            int idx = tid + it * 512;
            int r = idx >> 3, u = idx & 7;
            *reinterpret_cast<uint4*>(&Ab[r * 72 + u * 8]) = ra[it];
            *reinterpret_cast<uint4*>(&Bb[r * 72 + u * 8]) = rb[it];
        }
        __syncthreads();

        if (kc8 < 7) {
            int kc = (kc8 + 1) * 64;
            #pragma unroll
            for (int it = 0; it < 2; it++) {
                int idx = tid + it * 512;
                int r = idx >> 3, u = idx & 7;
                ra[it] = *reinterpret_cast<const uint4*>(
                    X + (size_t)(row0 + r) * DM + kc + u * 8);
                rb[it] = *reinterpret_cast<const uint4*>(
                    W + (size_t)(j0 + r) * DM + kc + u * 8);
            }
        }

        #pragma unroll
        for (int kt = 0; kt < 4; kt++) {
            unsigned af[2][4], bf0[4], bf1[4];
            #pragma unroll
            for (int mt = 0; mt < 2; mt++)
                ldsm_x4(af[mt], Ab, wn * 32 + mt * 16, kt * 16, 72, lane);
            ldsm_b_x4n(bf0, Bb, wc * 32, kt * 16, 72, lane);       // nt 0,1
            ldsm_b_x4n(bf1, Bb, wc * 32 + 16, kt * 16, 72, lane);  // nt 2,3
            #pragma unroll
            for (int mt = 0; mt < 2; mt++) {
                mma16816(acc[mt][0], af[mt], bf0);
                mma16816(acc[mt][1], af[mt], bf0 + 2);
                mma16816(acc[mt][2], af[mt], bf1);
                mma16816(acc[mt][3], af[mt], bf1 + 2);
            }
        }
        // next iter's barrier (other buffer) orders reads vs overwrite
    }

    const int h = blockIdx.y * 2 + (wc >> 1);         // warp-uniform head
    #pragma unroll
    for (int mt = 0; mt < 2; mt++) {
        int rg = row0 + wn * 32 + mt * 16 + (lane >> 2);
        #pragma unroll
        for (int nt = 0; nt < 4; nt++) {
            int j = j0 + wc * 32 + nt * 8 + 2 * (lane & 3);
            int c = j & 63;
            float b0 = __ldg(bias + j), b1 = __ldg(bias + j + 1);
            #pragma unroll
            for (int hr = 0; hr < 2; hr++) {
                int r = rg + hr * 8;
                int bi = r >> 10, seq = r & 1023;
                float v0 = acc[mt][nt][hr * 2 + 0] + b0;
                float v1 = acc[mt][nt][hr * 2 + 1] + b1;
                size_t bh = (size_t)(bi * HH + h);
                if (which == 2) {
                    vt_g[(bh * CC + c) * MM + seq]     = __float2half_rn(v0);
                    vt_g[(bh * CC + c + 1) * MM + seq] = __float2half_rn(v1);
                } else {
                    __half* dst = (which == 0) ? qh_g : kh_g;
                    *reinterpret_cast<__half2*>(&dst[(bh * NN + seq) * CC + c]) =
                        __floats2half2_rn(v0, v1);
                }
            }
        }
    }
}

// =====================================================================
// Kernel 2 (FUSED, R12 measured-best, byte-identical): fp16 Gs;
// double-buffered K / V+Ps; pass A row sums; pass B exp + attn + AV.
// grid (64, 8, 2) = 1024 CTAs, 512 thr, 2 CTAs/SM.
// =====================================================================
#define GS_STRIDE 1032
#define GS_OFF   0                               // 16 x 1032 f16 = 33024
#define KV_OFF   33024                           // 2 x 18432 (K 128x72 / V 64x136)
#define PS_OFF   69888                           // 2 x 17408 ([4][16][136] f16)
#define US_OFF   104704                          // 4 x 1056 f16 = 8448
#define US_STRIDE 1056
#define K2_SMEM  113152

__global__ __launch_bounds__(512, 2)
void attn_kernel(float* __restrict__ hidden_out, float* __restrict__ attn_out,
                 const float* __restrict__ qsub, const float* __restrict__ ksub) {
    extern __shared__ char smem[];
    __half* Gs = reinterpret_cast<__half*>(smem + GS_OFF);
    __half* qs = reinterpret_cast<__half*>(smem + PS_OFF);   // overlay (pre-pass-B)
    __half* us = reinterpret_cast<__half*>(smem + US_OFF);
    float*  red = reinterpret_cast<float*>(smem + KV_OFF);   // final reduction (buf0)

    const int n0 = blockIdx.x * 16;
    const int h = blockIdx.y, b = blockIdx.z;
    const size_t bh = (size_t)b * HH + h;
    const int tid = threadIdx.x, warp = tid >> 5, lane = tid & 31;

    // prefetch K chunk 0
    uint4 pk[2];
    #pragma unroll
    for (int it = 0; it < 2; it++) {
        int idx = tid + it * 512;
        int r = idx >> 3, u = idx & 7;
        pk[it] = *reinterpret_cast<const uint4*>(kh_g + (bh * MM + r) * CC + u * 8);
    }
    // stage q tile (16 x 64 f16)
    if (tid < 128) {
        int r = tid >> 3, u = tid & 7;
        *reinterpret_cast<uint4*>(&qs[r * 72 + u * 8]) =
            *reinterpret_cast<const uint4*>(qh_g + (bh * NN + n0 + r) * CC + u * 8);
    }
    // stage ksub fp16
    #pragma unroll
    for (int it = 0; it < 2; it++) {
        int idx = tid + it * 512;
        int s = idx >> 8, mf = (idx & 255) << 2;
        float4 d = __ldg(reinterpret_cast<const float4*>(
            ksub + ((size_t)b * SS + s) * MM + mf));
        __half2* dst = reinterpret_cast<__half2*>(&us[s * US_STRIDE + mf]);
        dst[0] = __floats2half2_rn(d.x, d.y);
        dst[1] = __floats2half2_rn(d.z, d.w);
    }
    __syncthreads();

    unsigned afr[4][4];
    #pragma unroll
    for (int kt = 0; kt < 4; kt++)
        ldsm_x4(afr[kt], qs, 0, kt * 16, 72, lane);

    // ---- QK: 8 chunks of 128 m, double-buffered K, one sync/chunk ----
    for (int mc = 0; mc < 8; mc++) {
        __half* kb = reinterpret_cast<__half*>(smem + KV_OFF + (mc & 1) * 18432);
        #pragma unroll
        for (int it = 0; it < 2; it++) {
            int idx = tid + it * 512;
            int r = idx >> 3, u = idx & 7;
            *reinterpret_cast<uint4*>(&kb[r * 72 + u * 8]) = pk[it];
        }
        if (mc < 7) {
            #pragma unroll
            for (int it = 0; it < 2; it++) {
                int idx = tid + it * 512;
                int r = idx >> 3, u = idx & 7;
                pk[it] = *reinterpret_cast<const uint4*>(
                    kh_g + (bh * MM + (mc + 1) * 128 + r) * CC + u * 8);
            }
        }
        __syncthreads();
        float acc[4] = {};
        #pragma unroll
        for (int kp = 0; kp < 2; kp++) {
            unsigned bfr[4];
            ldsm_b_x4k(bfr, kb, warp * 8, kp * 32, 72, lane);
            mma16816(acc, afr[kp * 2 + 0], bfr);
            mma16816(acc, afr[kp * 2 + 1], bfr + 2);
        }
        int r = lane >> 2;
        int c0 = mc * 128 + warp * 8 + 2 * (lane & 3);
        *reinterpret_cast<__half2*>(&Gs[r * GS_STRIDE + c0]) =
            __floats2half2_rn(acc[0], acc[1]);
        *reinterpret_cast<__half2*>(&Gs[(r + 8) * GS_STRIDE + c0]) =
            __floats2half2_rn(acc[2], acc[3]);
    }
    __syncthreads();

    // prefetch V chunk 0
    uint4 pv[2];
    #pragma unroll
    for (int it = 0; it < 2; it++) {
        int idx = tid + it * 512;
        int r = idx >> 4, u = idx & 15;
        pv[it] = *reinterpret_cast<const uint4*>(vt_g + (bh * CC + r) * MM + u * 8);
    }

    // ---- pass A: row sums (warp w owns row w) ----
    float cs[4], inv[4];
    #pragma unroll
    for (int s = 0; s < SS; s++)
        cs[s] = SCALE * __ldg(qsub + ((size_t)b * SS + s) * NN + n0 + warp);
    {
        float sum[4] = {0.f, 0.f, 0.f, 0.f};
        #pragma unroll
        for (int j = 0; j < 8; j++) {
            int m = j * 128 + lane * 4;
            uint2 gu = *reinterpret_cast<const uint2*>(&Gs[warp * GS_STRIDE + m]);
            float2 g01 = __half22float2(*reinterpret_cast<__half2*>(&gu.x));
            float2 g23 = __half22float2(*reinterpret_cast<__half2*>(&gu.y));
            #pragma unroll
            for (int s = 0; s < SS; s++) {
                uint2 du = *reinterpret_cast<const uint2*>(&us[s * US_STRIDE + m]);
                float2 d01 = __half22float2(*reinterpret_cast<__half2*>(&du.x));
                float2 d23 = __half22float2(*reinterpret_cast<__half2*>(&du.y));
                sum[s] += __expf(cs[s] * d01.x * g01.x) + __expf(cs[s] * d01.y * g01.y)
                        + __expf(cs[s] * d23.x * g23.x) + __expf(cs[s] * d23.y * g23.y);
            }
        }
        #pragma unroll
        for (int s = 0; s < SS; s++) {
            #pragma unroll
            for (int o = 16; o; o >>= 1)
                sum[s] += __shfl_xor_sync(0xffffffffu, sum[s], o);
            inv[s] = 1.f / sum[s];
        }
    }

    // ---- pass B: double-buffered V + Ps, one sync/chunk ----
    float accB[4][4] = {};
    const int s_own = warp >> 2;
    const int kh_ = (warp >> 1) & 1;
    const int ng = warp & 1;

    for (int mc = 0; mc < 8; mc++) {
        __half* vb = reinterpret_cast<__half*>(smem + KV_OFF + (mc & 1) * 18432);
        __half* pb = reinterpret_cast<__half*>(smem + PS_OFF + (mc & 1) * 17408);
        #pragma unroll
        for (int it = 0; it < 2; it++) {
            int idx = tid + it * 512;
            int r = idx >> 4, u = idx & 15;
            *reinterpret_cast<uint4*>(&vb[r * 136 + u * 8]) = pv[it];
        }
        {
            int m = mc * 128 + lane * 4;
            uint2 gu = *reinterpret_cast<const uint2*>(&Gs[warp * GS_STRIDE + m]);
            float2 g01 = __half22float2(*reinterpret_cast<__half2*>(&gu.x));
            float2 g23 = __half22float2(*reinterpret_cast<__half2*>(&gu.y));
            #pragma unroll
            for (int s = 0; s < SS; s++) {
                uint2 du = *reinterpret_cast<const uint2*>(&us[s * US_STRIDE + m]);
                float2 d01 = __half22float2(*reinterpret_cast<__half2*>(&du.x));
                float2 d23 = __half22float2(*reinterpret_cast<__half2*>(&du.y));
                float4 e;
                e.x = __expf(cs[s] * d01.x * g01.x) * inv[s];
                e.y = __expf(cs[s] * d01.y * g01.y) * inv[s];
                e.z = __expf(cs[s] * d23.x * g23.x) * inv[s];
                e.w = __expf(cs[s] * d23.y * g23.y) * inv[s];
                __stcs(reinterpret_cast<float4*>(
                    attn_out + ((bh * SS + s) * NN + n0 + warp) * (size_t)MM + m), e);
                __half2* pd = reinterpret_cast<__half2*>(&pb[(s * 16 + warp) * 136 + lane * 4]);
                pd[0] = __floats2half2_rn(e.x, e.y);
                pd[1] = __floats2half2_rn(e.z, e.w);
            }
        }
        if (mc < 7) {
            #pragma unroll
            for (int it = 0; it < 2; it++) {
                int idx = tid + it * 512;
                int r = idx >> 4, u = idx & 15;
                pv[it] = *reinterpret_cast<const uint4*>(
                    vt_g + (bh * CC + r) * MM + (mc + 1) * 128 + u * 8);
            }
        }
        __syncthreads();
        #pragma unroll
        for (int kt = 0; kt < 4; kt++) {
            int kk = kh_ * 4 + kt;
            unsigned af[4];
            ldsm_x4(af, pb + s_own * 16 * 136, 0, kk * 16, 136, lane);
            unsigned bf0[4], bf1[4];
            ldsm_b_x4n(bf0, vb, ng * 32, kk * 16, 136, lane);
            ldsm_b_x4n(bf1, vb, ng * 32 + 16, kk * 16, 136, lane);
            mma16816(accB[0], af, bf0);
            mma16816(accB[1], af, bf0 + 2);
            mma16816(accB[2], af, bf1);
            mma16816(accB[3], af, bf1 + 2);
        }
    }
    __syncthreads();

    // 2-way k-split reduction + hidden write (red overlays buf0)
    if (kh_ == 1) {
        #pragma unroll
        for (int nt = 0; nt < 4; nt++)
            *reinterpret_cast<float4*>(
                &red[(((s_own * 2 + ng) * 4 + nt) * 32 + lane) * 4]) =
                make_float4(accB[nt][0], accB[nt][1], accB[nt][2], accB[nt][3]);
    }
    __syncthreads();
    if (kh_ == 0) {
        #pragma unroll
        for (int nt = 0; nt < 4; nt++) {
            float4 p = *reinterpret_cast<const float4*>(
                &red[(((s_own * 2 + ng) * 4 + nt) * 32 + lane) * 4]);
            float v0 = accB[nt][0] + p.x, v1 = accB[nt][1] + p.y;
            float v2 = accB[nt][2] + p.z, v3 = accB[nt][3] + p.w;
            int r0 = lane >> 2;
            int c = ng * 32 + nt * 8 + 2 * (lane & 3);
            size_t base = ((size_t)(b * SS + s_own) * NN + n0) * DM + h * 64 + c;
            *reinterpret_cast<float2*>(&hidden_out[base + (size_t)r0 * DM]) =
                make_float2(v0, v1);
            *reinterpret_cast<float2*>(&hidden_out[base + (size_t)(r0 + 8) * DM]) =
                make_float2(v2, v3);
        }
    }
}

// =====================================================================
extern "C" void kernel_launch(void* const* d_in, const int* in_sizes, int n_in,
                              void* d_out, int out_size) {
    (void)in_sizes; (void)n_in; (void)out_size;
    const float* Xq   = (const float*)d_in[0];
    const float* Xk   = (const float*)d_in[1];
    const float* Xv   = (const float*)d_in[2];
    const float* qsub = (const float*)d_in[3];
    const float* ksub = (const float*)d_in[4];
    const float* Wq   = (const float*)d_in[5];
    const float* bq   = (const float*)d_in[6];
    const float* Wk   = (const float*)d_in[7];
    const float* bk   = (const float*)d_in[8];
    const float* Wv   = (const float*)d_in[9];
    const float* bv   = (const float*)d_in[10];

    float* out = (float*)d_out;
    float* attn_out = out + (size_t)BB * SS * NN * DM;  // hidden first, attn second

    cudaFuncSetAttribute(attn_kernel, cudaFuncAttributeMaxDynamicSharedMemorySize, K2_SMEM);

    convert_kernel<<<(X4_TOT + 255) / 256, 256>>>(Xq, Xk, Xv, Wq, Wk, Wv);
    proj_kernel<<<dim3(16, 4, 3), 512>>>(bq, bk, bv);
    attn_kernel<<<dim3(64, 8, 2), 512, K2_SMEM>>>(out, attn_out, qsub, ksub);
}

// round 15
// speedup vs baseline: 1.0200x; 1.0200x over previous
#include <cuda_runtime.h>
#include <cuda_fp16.h>

// Problem constants
#define BB 2
#define HH 8
#define NN 1024
#define MM 1024
#define SS 4
#define CC 64
#define DM 512
#define SCALE 0.125f   // 1/sqrt(64)

// fp16 scratch (device globals: allocation-free)
__device__ __half qh_g[(size_t)BB*HH*NN*CC];   // [bh][n][c]
__device__ __half kh_g[(size_t)BB*HH*MM*CC];   // [bh][m][c]
__device__ __half vt_g[(size_t)BB*HH*CC*MM];   // [bh][c][m]  (transposed V)
__device__ __half xh_g[(size_t)3*BB*NN*DM];    // fp16 inputs  [which][row][d]
__device__ __half wh_g[(size_t)3*DM*DM];       // fp16 weights [which][j][d]

// ---------------------------------------------------------------- mma helpers
__device__ __forceinline__ unsigned smem_u32(const void* p) {
    return (unsigned)__cvta_generic_to_shared(p);
}

__device__ __forceinline__ void ldsm_x4(unsigned r[4], const __half* base,
                                        int row, int col, int ld, int lane) {
    const __half* p = base + (size_t)(row + (lane & 7) + ((lane >> 3) & 1) * 8) * ld
                           + col + (lane >> 4) * 8;
    unsigned a = smem_u32(p);
    asm volatile("ldmatrix.sync.aligned.m8n8.x4.shared.b16 {%0,%1,%2,%3},[%4];\n"
                 : "=r"(r[0]), "=r"(r[1]), "=r"(r[2]), "=r"(r[3]) : "r"(a));
}

// B-frag pair over two n-tiles (nrow, nrow+8), same kcol
__device__ __forceinline__ void ldsm_b_x4n(unsigned r[4], const __half* base,
                                           int nrow, int kcol, int ld, int lane) {
    const __half* p = base + (size_t)(nrow + (lane & 7) + ((lane >> 4) & 1) * 8) * ld
                           + kcol + ((lane >> 3) & 1) * 8;
    unsigned a = smem_u32(p);
    asm volatile("ldmatrix.sync.aligned.m8n8.x4.shared.b16 {%0,%1,%2,%3},[%4];\n"
                 : "=r"(r[0]), "=r"(r[1]), "=r"(r[2]), "=r"(r[3]) : "r"(a));
}

// B-frag pair over two k-tiles (kcol, kcol+16), same nrow
__device__ __forceinline__ void ldsm_b_x4k(unsigned r[4], const __half* base,
                                           int nrow, int kcol, int ld, int lane) {
    const __half* p = base + (size_t)(nrow + (lane & 7)) * ld
                           + kcol + ((lane >> 3) & 1) * 8 + ((lane >> 4) & 1) * 16;
    unsigned a = smem_u32(p);
    asm volatile("ldmatrix.sync.aligned.m8n8.x4.shared.b16 {%0,%1,%2,%3},[%4];\n"
                 : "=r"(r[0]), "=r"(r[1]), "=r"(r[2]), "=r"(r[3]) : "r"(a));
}

__device__ __forceinline__ void mma16816(float c[4], const unsigned a[4], const unsigned b[2]) {
    asm volatile("mma.sync.aligned.m16n8k16.row.col.f32.f16.f16.f32 "
                 "{%0,%1,%2,%3},{%4,%5,%6,%7},{%8,%9},{%0,%1,%2,%3};\n"
                 : "+f"(c[0]), "+f"(c[1]), "+f"(c[2]), "+f"(c[3])
                 : "r"(a[0]), "r"(a[1]), "r"(a[2]), "r"(a[3]), "r"(b[0]), "r"(b[1]));
}

// =====================================================================
// Kernel 0: convert X and W to fp16.
// =====================================================================
#define X4_PERX (BB * NN * DM / 4)
#define X4_PERW (DM * DM / 4)
#define X4_XTOT (3 * X4_PERX)
#define X4_TOT  (X4_XTOT + 3 * X4_PERW)

__global__ __launch_bounds__(256)
void convert_kernel(const float* __restrict__ Xq, const float* __restrict__ Xk,
                    const float* __restrict__ Xv, const float* __restrict__ Wq,
                    const float* __restrict__ Wk, const float* __restrict__ Wv) {
    int idx = blockIdx.x * 256 + threadIdx.x;
    if (idx >= X4_TOT) return;
    float4 v;
    __half* dst;
    if (idx < X4_XTOT) {
        int which = idx / X4_PERX, off = idx - which * X4_PERX;
        const float* src = (which == 0) ? Xq : (which == 1) ? Xk : Xv;
        v = __ldg(reinterpret_cast<const float4*>(src) + off);
        dst = xh_g + (size_t)which * (BB * NN * DM) + (size_t)off * 4;
    } else {
        int j = idx - X4_XTOT;
        int which = j / X4_PERW, off = j - which * X4_PERW;
        const float* src = (which == 0) ? Wq : (which == 1) ? Wk : Wv;
        v = __ldg(reinterpret_cast<const float4*>(src) + off);
        dst = wh_g + (size_t)which * (DM * DM) + (size_t)off * 4;
    }
    __half2* d2 = reinterpret_cast<__half2*>(dst);
    d2[0] = __floats2half2_rn(v.x, v.y);
    d2[1] = __floats2half2_rn(v.z, v.w);
}

// =====================================================================
// Kernel 1: projections from fp16, 128x128 tiles (TK=64), double-buffered.
// grid (16, 4, 3) = 192 CTAs, 512 threads; NO min-blocks clause -> ~85
// regs, no spills, 1 CTA/SM via RF.
// =====================================================================
__global__ __launch_bounds__(512)
void proj_kernel(const float* __restrict__ bq, const float* __restrict__ bk,
                 const float* __restrict__ bv) {
    const int which = blockIdx.z;
    const __half* X = xh_g + (size_t)which * (BB * NN * DM);
    const __half* W = wh_g + (size_t)which * (DM * DM);
    const float* bias = (which == 0) ? bq : (which == 1) ? bk : bv;

    __shared__ __half As[2 * 128 * 72];   // 36864 B
    __shared__ __half Bs[2 * 128 * 72];   // 36864 B

    const int row0 = blockIdx.x * 128;
    const int j0 = blockIdx.y * 128;      // spans heads 2*by, 2*by+1
    const int tid = threadIdx.x;
    const int warp = tid >> 5, lane = tid & 31;
    const int wn = warp & 3, wc = warp >> 2;   // 4x4 warps, 32x32 per warp

    float acc[2][4][4] = {};
    uint4 ra[2], rb[2];

    // staging: 128 rows x 8 uint4 per matrix, 2/thread
    #pragma unroll
    for (int it = 0; it < 2; it++) {
        int idx = tid + it * 512;
        int r = idx >> 3, u = idx & 7;
        ra[it] = *reinterpret_cast<const uint4*>(X + (size_t)(row0 + r) * DM + u * 8);
        rb[it] = *reinterpret_cast<const uint4*>(W + (size_t)(j0 + r) * DM + u * 8);
    }

    for (int kc8 = 0; kc8 < 8; kc8++) {
        __half* Ab = As + (kc8 & 1) * 128 * 72;
        __half* Bb = Bs + (kc8 & 1) * 128 * 72;
        #pragma unroll
        for (int it = 0; it < 2; it++) {
            int idx = tid + it * 512;
            int r = idx >> 3, u = idx & 7;
            *reinterpret_cast<uint4*>(&Ab[r * 72 + u * 8]) = ra[it];
            *reinterpret_cast<uint4*>(&Bb[r * 72 + u * 8]) = rb[it];
        }
        __syncthreads();

        if (kc8 < 7) {
            int kc = (kc8 + 1) * 64;
            #pragma unroll
            for (int it = 0; it < 2; it++) {
                int idx = tid + it * 512;
                int r = idx >> 3, u = idx & 7;
                ra[it] = *reinterpret_cast<const uint4*>(
                    X + (size_t)(row0 + r) * DM + kc + u * 8);
                rb[it] = *reinterpret_cast<const uint4*>(
                    W + (size_t)(j0 + r) * DM + kc + u * 8);
            }
        }

        #pragma unroll
        for (int kt = 0; kt < 4; kt++) {
            unsigned af[2][4], bf0[4], bf1[4];
            #pragma unroll
            for (int mt = 0; mt < 2; mt++)
                ldsm_x4(af[mt], Ab, wn * 32 + mt * 16, kt * 16, 72, lane);
            ldsm_b_x4n(bf0, Bb, wc * 32, kt * 16, 72, lane);       // nt 0,1
            ldsm_b_x4n(bf1, Bb, wc * 32 + 16, kt * 16, 72, lane);  // nt 2,3
            #pragma unroll
            for (int mt = 0; mt < 2; mt++) {
                mma16816(acc[mt][0], af[mt], bf0);
                mma16816(acc[mt][1], af[mt], bf0 + 2);
                mma16816(acc[mt][2], af[mt], bf1);
                mma16816(acc[mt][3], af[mt], bf1 + 2);
            }
        }
        // next iter's barrier (other buffer) orders reads vs overwrite
    }

    const int h = blockIdx.y * 2 + (wc >> 1);         // warp-uniform head
    #pragma unroll
    for (int mt = 0; mt < 2; mt++) {
        int rg = row0 + wn * 32 + mt * 16 + (lane >> 2);
        #pragma unroll
        for (int nt = 0; nt < 4; nt++) {
            int j = j0 + wc * 32 + nt * 8 + 2 * (lane & 3);
            int c = j & 63;
            float b0 = __ldg(bias + j), b1 = __ldg(bias + j + 1);
            #pragma unroll
            for (int hr = 0; hr < 2; hr++) {
                int r = rg + hr * 8;
                int bi = r >> 10, seq = r & 1023;
                float v0 = acc[mt][nt][hr * 2 + 0] + b0;
                float v1 = acc[mt][nt][hr * 2 + 1] + b1;
                size_t bh = (size_t)(bi * HH + h);
                if (which == 2) {
                    vt_g[(bh * CC + c) * MM + seq]     = __float2half_rn(v0);
                    vt_g[(bh * CC + c + 1) * MM + seq] = __float2half_rn(v1);
                } else {
                    __half* dst = (which == 0) ? qh_g : kh_g;
                    *reinterpret_cast<__half2*>(&dst[(bh * NN + seq) * CC + c]) =
                        __floats2half2_rn(v0, v1);
                }
            }
        }
    }
}

// =====================================================================
// Kernel 2 (FUSED, R12 measured-best, byte-identical): fp16 Gs;
// double-buffered K / V+Ps; pass A row sums; pass B exp + attn + AV.
// grid (64, 8, 2) = 1024 CTAs, 512 thr, 2 CTAs/SM.
// =====================================================================
#define GS_STRIDE 1032
#define GS_OFF   0                               // 16 x 1032 f16 = 33024
#define KV_OFF   33024                           // 2 x 18432 (K 128x72 / V 64x136)
#define PS_OFF   69888                           // 2 x 17408 ([4][16][136] f16)
#define US_OFF   104704                          // 4 x 1056 f16 = 8448
#define US_STRIDE 1056
#define K2_SMEM  113152

__global__ __launch_bounds__(512, 2)
void attn_kernel(float* __restrict__ hidden_out, float* __restrict__ attn_out,
                 const float* __restrict__ qsub, const float* __restrict__ ksub) {
    extern __shared__ char smem[];
    __half* Gs = reinterpret_cast<__half*>(smem + GS_OFF);
    __half* qs = reinterpret_cast<__half*>(smem + PS_OFF);   // overlay (pre-pass-B)
    __half* us = reinterpret_cast<__half*>(smem + US_OFF);
    float*  red = reinterpret_cast<float*>(smem + KV_OFF);   // final reduction (buf0)

    const int n0 = blockIdx.x * 16;
    const int h = blockIdx.y, b = blockIdx.z;
    const size_t bh = (size_t)b * HH + h;
    const int tid = threadIdx.x, warp = tid >> 5, lane = tid & 31;

    // prefetch K chunk 0
    uint4 pk[2];
    #pragma unroll
    for (int it = 0; it < 2; it++) {
        int idx = tid + it * 512;
        int r = idx >> 3, u = idx & 7;
        pk[it] = *reinterpret_cast<const uint4*>(kh_g + (bh * MM + r) * CC + u * 8);
    }
    // stage q tile (16 x 64 f16)
    if (tid < 128) {
        int r = tid >> 3, u = tid & 7;
        *reinterpret_cast<uint4*>(&qs[r * 72 + u * 8]) =
            *reinterpret_cast<const uint4*>(qh_g + (bh * NN + n0 + r) * CC + u * 8);
    }
    // stage ksub fp16
    #pragma unroll
    for (int it = 0; it < 2; it++) {
        int idx = tid + it * 512;
        int s = idx >> 8, mf = (idx & 255) << 2;
        float4 d = __ldg(reinterpret_cast<const float4*>(
            ksub + ((size_t)b * SS + s) * MM + mf));
        __half2* dst = reinterpret_cast<__half2*>(&us[s * US_STRIDE + mf]);
        dst[0] = __floats2half2_rn(d.x, d.y);
        dst[1] = __floats2half2_rn(d.z, d.w);
    }
    __syncthreads();

    unsigned afr[4][4];
    #pragma unroll
    for (int kt = 0; kt < 4; kt++)
        ldsm_x4(afr[kt], qs, 0, kt * 16, 72, lane);

    // ---- QK: 8 chunks of 128 m, double-buffered K, one sync/chunk ----
    for (int mc = 0; mc < 8; mc++) {
        __half* kb = reinterpret_cast<__half*>(smem + KV_OFF + (mc & 1) * 18432);
        #pragma unroll
        for (int it = 0; it < 2; it++) {
            int idx = tid + it * 512;
            int r = idx >> 3, u = idx & 7;
            *reinterpret_cast<uint4*>(&kb[r * 72 + u * 8]) = pk[it];
        }
        if (mc < 7) {
            #pragma unroll
            for (int it = 0; it < 2; it++) {
                int idx = tid + it * 512;
                int r = idx >> 3, u = idx & 7;
                pk[it] = *reinterpret_cast<const uint4*>(
                    kh_g + (bh * MM + (mc + 1) * 128 + r) * CC + u * 8);
            }
        }
        __syncthreads();
        float acc[4] = {};
        #pragma unroll
        for (int kp = 0; kp < 2; kp++) {
            unsigned bfr[4];
            ldsm_b_x4k(bfr, kb, warp * 8, kp * 32, 72, lane);
            mma16816(acc, afr[kp * 2 + 0], bfr);
            mma16816(acc, afr[kp * 2 + 1], bfr + 2);
        }
        int r = lane >> 2;
        int c0 = mc * 128 + warp * 8 + 2 * (lane & 3);
        *reinterpret_cast<__half2*>(&Gs[r * GS_STRIDE + c0]) =
            __floats2half2_rn(acc[0], acc[1]);
        *reinterpret_cast<__half2*>(&Gs[(r + 8) * GS_STRIDE + c0]) =
            __floats2half2_rn(acc[2], acc[3]);
    }
    __syncthreads();

    // prefetch V chunk 0
    uint4 pv[2];
    #pragma unroll
    for (int it = 0; it < 2; it++) {
        int idx = tid + it * 512;
        int r = idx >> 4, u = idx & 15;
        pv[it] = *reinterpret_cast<const uint4*>(vt_g + (bh * CC + r) * MM + u * 8);
    }

    // ---- pass A: row sums (warp w owns row w) ----
    float cs[4], inv[4];
    #pragma unroll
    for (int s = 0; s < SS; s++)
        cs[s] = SCALE * __ldg(qsub + ((size_t)b * SS + s) * NN + n0 + warp);
    {
        float sum[4] = {0.f, 0.f, 0.f, 0.f};
        #pragma unroll
        for (int j = 0; j < 8; j++) {
            int m = j * 128 + lane * 4;
            uint2 gu = *reinterpret_cast<const uint2*>(&Gs[warp * GS_STRIDE + m]);
            float2 g01 = __half22float2(*reinterpret_cast<__half2*>(&gu.x));
            float2 g23 = __half22float2(*reinterpret_cast<__half2*>(&gu.y));
            #pragma unroll
            for (int s = 0; s < SS; s++) {
                uint2 du = *reinterpret_cast<const uint2*>(&us[s * US_STRIDE + m]);
                float2 d01 = __half22float2(*reinterpret_cast<__half2*>(&du.x));
                float2 d23 = __half22float2(*reinterpret_cast<__half2*>(&du.y));
                sum[s] += __expf(cs[s] * d01.x * g01.x) + __expf(cs[s] * d01.y * g01.y)
                        + __expf(cs[s] * d23.x * g23.x) + __expf(cs[s] * d23.y * g23.y);
            }
        }
        #pragma unroll
        for (int s = 0; s < SS; s++) {
            #pragma unroll
            for (int o = 16; o; o >>= 1)
                sum[s] += __shfl_xor_sync(0xffffffffu, sum[s], o);
            inv[s] = 1.f / sum[s];
        }
    }

    // ---- pass B: double-buffered V + Ps, one sync/chunk ----
    float accB[4][4] = {};
    const int s_own = warp >> 2;
    const int kh_ = (warp >> 1) & 1;
    const int ng = warp & 1;

    for (int mc = 0; mc < 8; mc++) {
        __half* vb = reinterpret_cast<__half*>(smem + KV_OFF + (mc & 1) * 18432);
        __half* pb = reinterpret_cast<__half*>(smem + PS_OFF + (mc & 1) * 17408);
        #pragma unroll
        for (int it = 0; it < 2; it++) {
            int idx = tid + it * 512;
            int r = idx >> 4, u = idx & 15;
            *reinterpret_cast<uint4*>(&vb[r * 136 + u * 8]) = pv[it];
        }
        {
            int m = mc * 128 + lane * 4;
            uint2 gu = *reinterpret_cast<const uint2*>(&Gs[warp * GS_STRIDE + m]);
            float2 g01 = __half22float2(*reinterpret_cast<__half2*>(&gu.x));
            float2 g23 = __half22float2(*reinterpret_cast<__half2*>(&gu.y));
            #pragma unroll
            for (int s = 0; s < SS; s++) {
                uint2 du = *reinterpret_cast<const uint2*>(&us[s * US_STRIDE + m]);
                float2 d01 = __half22float2(*reinterpret_cast<__half2*>(&du.x));
                float2 d23 = __half22float2(*reinterpret_cast<__half2*>(&du.y));
                float4 e;
                e.x = __expf(cs[s] * d01.x * g01.x) * inv[s];
                e.y = __expf(cs[s] * d01.y * g01.y) * inv[s];
                e.z = __expf(cs[s] * d23.x * g23.x) * inv[s];
                e.w = __expf(cs[s] * d23.y * g23.y) * inv[s];
                __stcs(reinterpret_cast<float4*>(
                    attn_out + ((bh * SS + s) * NN + n0 + warp) * (size_t)MM + m), e);
                __half2* pd = reinterpret_cast<__half2*>(&pb[(s * 16 + warp) * 136 + lane * 4]);
                pd[0] = __floats2half2_rn(e.x, e.y);
                pd[1] = __floats2half2_rn(e.z, e.w);
            }
        }
        if (mc < 7) {
            #pragma unroll
            for (int it = 0; it < 2; it++) {
                int idx = tid + it * 512;
                int r = idx >> 4, u = idx & 15;
                pv[it] = *reinterpret_cast<const uint4*>(
                    vt_g + (bh * CC + r) * MM + (mc + 1) * 128 + u * 8);
            }
        }
        __syncthreads();
        #pragma unroll
        for (int kt = 0; kt < 4; kt++) {
            int kk = kh_ * 4 + kt;
            unsigned af[4];
            ldsm_x4(af, pb + s_own * 16 * 136, 0, kk * 16, 136, lane);
            unsigned bf0[4], bf1[4];
            ldsm_b_x4n(bf0, vb, ng * 32, kk * 16, 136, lane);
            ldsm_b_x4n(bf1, vb, ng * 32 + 16, kk * 16, 136, lane);
            mma16816(accB[0], af, bf0);
            mma16816(accB[1], af, bf0 + 2);
            mma16816(accB[2], af, bf1);
            mma16816(accB[3], af, bf1 + 2);
        }
    }
    __syncthreads();

    // 2-way k-split reduction + hidden write (red overlays buf0)
    if (kh_ == 1) {
        #pragma unroll
        for (int nt = 0; nt < 4; nt++)
            *reinterpret_cast<float4*>(
                &red[(((s_own * 2 + ng) * 4 + nt) * 32 + lane) * 4]) =
                make_float4(accB[nt][0], accB[nt][1], accB[nt][2], accB[nt][3]);
    }
    __syncthreads();
    if (kh_ == 0) {
        #pragma unroll
        for (int nt = 0; nt < 4; nt++) {
            float4 p = *reinterpret_cast<const float4*>(
                &red[(((s_own * 2 + ng) * 4 + nt) * 32 + lane) * 4]);
            float v0 = accB[nt][0] + p.x, v1 = accB[nt][1] + p.y;
            float v2 = accB[nt][2] + p.z, v3 = accB[nt][3] + p.w;
            int r0 = lane >> 2;
            int c = ng * 32 + nt * 8 + 2 * (lane & 3);
            size_t base = ((size_t)(b * SS + s_own) * NN + n0) * DM + h * 64 + c;
            *reinterpret_cast<float2*>(&hidden_out[base + (size_t)r0 * DM]) =
                make_float2(v0, v1);
            *reinterpret_cast<float2*>(&hidden_out[base + (size_t)(r0 + 8) * DM]) =
                make_float2(v2, v3);
        }
    }
}

// =====================================================================
extern "C" void kernel_launch(void* const* d_in, const int* in_sizes, int n_in,
                              void* d_out, int out_size) {
    (void)in_sizes; (void)n_in; (void)out_size;
    const float* Xq   = (const float*)d_in[0];
    const float* Xk   = (const float*)d_in[1];
    const float* Xv   = (const float*)d_in[2];
    const float* qsub = (const float*)d_in[3];
    const float* ksub = (const float*)d_in[4];
    const float* Wq   = (const float*)d_in[5];
    const float* bq   = (const float*)d_in[6];
    const float* Wk   = (const float*)d_in[7];
    const float* bk   = (const float*)d_in[8];
    const float* Wv   = (const float*)d_in[9];
    const float* bv   = (const float*)d_in[10];

    float* out = (float*)d_out;
    float* attn_out = out + (size_t)BB * SS * NN * DM;  // hidden first, attn second

    cudaFuncSetAttribute(attn_kernel, cudaFuncAttributeMaxDynamicSharedMemorySize, K2_SMEM);

    convert_kernel<<<(X4_TOT + 255) / 256, 256>>>(Xq, Xk, Xv, Wq, Wk, Wv);
    proj_kernel<<<dim3(16, 4, 3), 512>>>(bq, bk, bv);
    attn_kernel<<<dim3(64, 8, 2), 512, K2_SMEM>>>(out, attn_out, qsub, ksub);
}

// round 16
// speedup vs baseline: 1.0340x; 1.0137x over previous
#include <cuda_runtime.h>
#include <cuda_fp16.h>

// Problem constants
#define BB 2
#define HH 8
#define NN 1024
#define MM 1024
#define SS 4
#define CC 64
#define DM 512
#define SCALE 0.125f   // 1/sqrt(64)

// fp16 scratch (device globals: allocation-free)
__device__ __half qh_g[(size_t)BB*HH*NN*CC];   // [bh][n][c]
__device__ __half kh_g[(size_t)BB*HH*MM*CC];   // [bh][m][c]
__device__ __half vt_g[(size_t)BB*HH*CC*MM];   // [bh][c][m]  (transposed V)

// ---------------------------------------------------------------- mma helpers
__device__ __forceinline__ unsigned smem_u32(const void* p) {
    return (unsigned)__cvta_generic_to_shared(p);
}

__device__ __forceinline__ void ldsm_x4(unsigned r[4], const __half* base,
                                        int row, int col, int ld, int lane) {
    const __half* p = base + (size_t)(row + (lane & 7) + ((lane >> 3) & 1) * 8) * ld
                           + col + (lane >> 4) * 8;
    unsigned a = smem_u32(p);
    asm volatile("ldmatrix.sync.aligned.m8n8.x4.shared.b16 {%0,%1,%2,%3},[%4];\n"
                 : "=r"(r[0]), "=r"(r[1]), "=r"(r[2]), "=r"(r[3]) : "r"(a));
}

// B-frag pair over two n-tiles (nrow, nrow+8), same kcol
__device__ __forceinline__ void ldsm_b_x4n(unsigned r[4], const __half* base,
                                           int nrow, int kcol, int ld, int lane) {
    const __half* p = base + (size_t)(nrow + (lane & 7) + ((lane >> 4) & 1) * 8) * ld
                           + kcol + ((lane >> 3) & 1) * 8;
    unsigned a = smem_u32(p);
    asm volatile("ldmatrix.sync.aligned.m8n8.x4.shared.b16 {%0,%1,%2,%3},[%4];\n"
                 : "=r"(r[0]), "=r"(r[1]), "=r"(r[2]), "=r"(r[3]) : "r"(a));
}

// B-frag pair over two k-tiles (kcol, kcol+16), same nrow
__device__ __forceinline__ void ldsm_b_x4k(unsigned r[4], const __half* base,
                                           int nrow, int kcol, int ld, int lane) {
    const __half* p = base + (size_t)(nrow + (lane & 7)) * ld
                           + kcol + ((lane >> 3) & 1) * 8 + ((lane >> 4) & 1) * 16;
    unsigned a = smem_u32(p);
    asm volatile("ldmatrix.sync.aligned.m8n8.x4.shared.b16 {%0,%1,%2,%3},[%4];\n"
                 : "=r"(r[0]), "=r"(r[1]), "=r"(r[2]), "=r"(r[3]) : "r"(a));
}

__device__ __forceinline__ void mma16816(float c[4], const unsigned a[4], const unsigned b[2]) {
    asm volatile("mma.sync.aligned.m16n8k16.row.col.f32.f16.f16.f32 "
                 "{%0,%1,%2,%3},{%4,%5,%6,%7},{%8,%9},{%0,%1,%2,%3};\n"
                 : "+f"(c[0]), "+f"(c[1]), "+f"(c[2]), "+f"(c[3])
                 : "r"(a[0]), "r"(a[1]), "r"(a[2]), "r"(a[3]), "r"(b[0]), "r"(b[1]));
}

// =====================================================================
// Kernel 1: projections direct from fp32, 128x128 tiles (TK=64),
// double-buffered, fp32->fp16 at staging (same rounding as before).
// grid (16, 4, 3) = 192 CTAs, 512 threads, no min-blocks clause.
// =====================================================================
__global__ __launch_bounds__(512)
void proj_kernel(const float* __restrict__ Xq, const float* __restrict__ Xk,
                 const float* __restrict__ Xv,
                 const float* __restrict__ Wq, const float* __restrict__ bq,
                 const float* __restrict__ Wk, const float* __restrict__ bk,
                 const float* __restrict__ Wv, const float* __restrict__ bv) {
    const int which = blockIdx.z;
    const float* X = (which == 0) ? Xq : (which == 1) ? Xk : Xv;
    const float* W = (which == 0) ? Wq : (which == 1) ? Wk : Wv;
    const float* bias = (which == 0) ? bq : (which == 1) ? bk : bv;

    __shared__ __half As[2 * 128 * 72];   // 36864 B
    __shared__ __half Bs[2 * 128 * 72];   // 36864 B

    const int row0 = blockIdx.x * 128;
    const int j0 = blockIdx.y * 128;      // spans heads 2*by, 2*by+1
    const int tid = threadIdx.x;
    const int warp = tid >> 5, lane = tid & 31;
    const int wn = warp & 3, wc = warp >> 2;   // 4x4 warps, 32x32 per warp

    float acc[2][4][4] = {};
    float4 ra[4], rb[4];

    // staging: 128 rows x 16 float4 per matrix = 2048 float4, 4/thread
    #pragma unroll
    for (int it = 0; it < 4; it++) {
        int idx = tid + it * 512;
        int r = idx >> 4, cf = (idx & 15) << 2;
        ra[it] = __ldg(reinterpret_cast<const float4*>(X + (size_t)(row0 + r) * DM + cf));
        rb[it] = __ldg(reinterpret_cast<const float4*>(W + (size_t)(j0 + r) * DM + cf));
    }

    for (int kc8 = 0; kc8 < 8; kc8++) {
        __half* Ab = As + (kc8 & 1) * 128 * 72;
        __half* Bb = Bs + (kc8 & 1) * 128 * 72;
        #pragma unroll
        for (int it = 0; it < 4; it++) {
            int idx = tid + it * 512;
            int r = idx >> 4, cf = (idx & 15) << 2;
            __half2* da = reinterpret_cast<__half2*>(&Ab[r * 72 + cf]);
            da[0] = __floats2half2_rn(ra[it].x, ra[it].y);
            da[1] = __floats2half2_rn(ra[it].z, ra[it].w);
            __half2* db = reinterpret_cast<__half2*>(&Bb[r * 72 + cf]);
            db[0] = __floats2half2_rn(rb[it].x, rb[it].y);
            db[1] = __floats2half2_rn(rb[it].z, rb[it].w);
        }
        __syncthreads();

        if (kc8 < 7) {
            int kc = (kc8 + 1) * 64;
            #pragma unroll
            for (int it = 0; it < 4; it++) {
                int idx = tid + it * 512;
                int r = idx >> 4, cf = (idx & 15) << 2;
                ra[it] = __ldg(reinterpret_cast<const float4*>(
                    X + (size_t)(row0 + r) * DM + kc + cf));
                rb[it] = __ldg(reinterpret_cast<const float4*>(
                    W + (size_t)(j0 + r) * DM + kc + cf));
            }
        }

        #pragma unroll
        for (int kt = 0; kt < 4; kt++) {
            unsigned af[2][4], bf0[4], bf1[4];
            #pragma unroll
            for (int mt = 0; mt < 2; mt++)
                ldsm_x4(af[mt], Ab, wn * 32 + mt * 16, kt * 16, 72, lane);
            ldsm_b_x4n(bf0, Bb, wc * 32, kt * 16, 72, lane);       // nt 0,1
            ldsm_b_x4n(bf1, Bb, wc * 32 + 16, kt * 16, 72, lane);  // nt 2,3
            #pragma unroll
            for (int mt = 0; mt < 2; mt++) {
                mma16816(acc[mt][0], af[mt], bf0);
                mma16816(acc[mt][1], af[mt], bf0 + 2);
                mma16816(acc[mt][2], af[mt], bf1);
                mma16816(acc[mt][3], af[mt], bf1 + 2);
            }
        }
        // next iter's barrier (other buffer) orders reads vs overwrite
    }

    const int h = blockIdx.y * 2 + (wc >> 1);         // warp-uniform head
    #pragma unroll
    for (int mt = 0; mt < 2; mt++) {
        int rg = row0 + wn * 32 + mt * 16 + (lane >> 2);
        #pragma unroll
        for (int nt = 0; nt < 4; nt++) {
            int j = j0 + wc * 32 + nt * 8 + 2 * (lane & 3);
            int c = j & 63;
            float b0 = __ldg(bias + j), b1 = __ldg(bias + j + 1);
            #pragma unroll
            for (int hr = 0; hr < 2; hr++) {
                int r = rg + hr * 8;
                int bi = r >> 10, seq = r & 1023;
                float v0 = acc[mt][nt][hr * 2 + 0] + b0;
                float v1 = acc[mt][nt][hr * 2 + 1] + b1;
                size_t bh = (size_t)(bi * HH + h);
                if (which == 2) {
                    vt_g[(bh * CC + c) * MM + seq]     = __float2half_rn(v0);
                    vt_g[(bh * CC + c + 1) * MM + seq] = __float2half_rn(v1);
                } else {
                    __half* dst = (which == 0) ? qh_g : kh_g;
                    *reinterpret_cast<__half2*>(&dst[(bh * NN + seq) * CC + c]) =
                        __floats2half2_rn(v0, v1);
                }
            }
        }
    }
}

// =====================================================================
// Kernel 2 (FUSED, R12 measured-best, byte-identical): fp16 Gs;
// double-buffered K / V+Ps; pass A row sums; pass B exp + attn + AV.
// grid (64, 8, 2) = 1024 CTAs, 512 thr, 2 CTAs/SM.
// =====================================================================
#define GS_STRIDE 1032
#define GS_OFF   0                               // 16 x 1032 f16 = 33024
#define KV_OFF   33024                           // 2 x 18432 (K 128x72 / V 64x136)
#define PS_OFF   69888                           // 2 x 17408 ([4][16][136] f16)
#define US_OFF   104704                          // 4 x 1056 f16 = 8448
#define US_STRIDE 1056
#define K2_SMEM  113152

__global__ __launch_bounds__(512, 2)
void attn_kernel(float* __restrict__ hidden_out, float* __restrict__ attn_out,
                 const float* __restrict__ qsub, const float* __restrict__ ksub) {
    extern __shared__ char smem[];
    __half* Gs = reinterpret_cast<__half*>(smem + GS_OFF);
    __half* qs = reinterpret_cast<__half*>(smem + PS_OFF);   // overlay (pre-pass-B)
    __half* us = reinterpret_cast<__half*>(smem + US_OFF);
    float*  red = reinterpret_cast<float*>(smem + KV_OFF);   // final reduction (buf0)

    const int n0 = blockIdx.x * 16;
    const int h = blockIdx.y, b = blockIdx.z;
    const size_t bh = (size_t)b * HH + h;
    const int tid = threadIdx.x, warp = tid >> 5, lane = tid & 31;

    // prefetch K chunk 0
    uint4 pk[2];
    #pragma unroll
    for (int it = 0; it < 2; it++) {
        int idx = tid + it * 512;
        int r = idx >> 3, u = idx & 7;
        pk[it] = *reinterpret_cast<const uint4*>(kh_g + (bh * MM + r) * CC + u * 8);
    }
    // stage q tile (16 x 64 f16)
    if (tid < 128) {
        int r = tid >> 3, u = tid & 7;
        *reinterpret_cast<uint4*>(&qs[r * 72 + u * 8]) =
            *reinterpret_cast<const uint4*>(qh_g + (bh * NN + n0 + r) * CC + u * 8);
    }
    // stage ksub fp16
    #pragma unroll
    for (int it = 0; it < 2; it++) {
        int idx = tid + it * 512;
        int s = idx >> 8, mf = (idx & 255) << 2;
        float4 d = __ldg(reinterpret_cast<const float4*>(
            ksub + ((size_t)b * SS + s) * MM + mf));
        __half2* dst = reinterpret_cast<__half2*>(&us[s * US_STRIDE + mf]);
        dst[0] = __floats2half2_rn(d.x, d.y);
        dst[1] = __floats2half2_rn(d.z, d.w);
    }
    __syncthreads();

    unsigned afr[4][4];
    #pragma unroll
    for (int kt = 0; kt < 4; kt++)
        ldsm_x4(afr[kt], qs, 0, kt * 16, 72, lane);

    // ---- QK: 8 chunks of 128 m, double-buffered K, one sync/chunk ----
    for (int mc = 0; mc < 8; mc++) {
        __half* kb = reinterpret_cast<__half*>(smem + KV_OFF + (mc & 1) * 18432);
        #pragma unroll
        for (int it = 0; it < 2; it++) {
            int idx = tid + it * 512;
            int r = idx >> 3, u = idx & 7;
            *reinterpret_cast<uint4*>(&kb[r * 72 + u * 8]) = pk[it];
        }
        if (mc < 7) {
            #pragma unroll
            for (int it = 0; it < 2; it++) {
                int idx = tid + it * 512;
                int r = idx >> 3, u = idx & 7;
                pk[it] = *reinterpret_cast<const uint4*>(
                    kh_g + (bh * MM + (mc + 1) * 128 + r) * CC + u * 8);
            }
        }
        __syncthreads();
        float acc[4] = {};
        #pragma unroll
        for (int kp = 0; kp < 2; kp++) {
            unsigned bfr[4];
            ldsm_b_x4k(bfr, kb, warp * 8, kp * 32, 72, lane);
            mma16816(acc, afr[kp * 2 + 0], bfr);
            mma16816(acc, afr[kp * 2 + 1], bfr + 2);
        }
        int r = lane >> 2;
        int c0 = mc * 128 + warp * 8 + 2 * (lane & 3);
        *reinterpret_cast<__half2*>(&Gs[r * GS_STRIDE + c0]) =
            __floats2half2_rn(acc[0], acc[1]);
        *reinterpret_cast<__half2*>(&Gs[(r + 8) * GS_STRIDE + c0]) =
            __floats2half2_rn(acc[2], acc[3]);
    }
    __syncthreads();

    // prefetch V chunk 0
    uint4 pv[2];
    #pragma unroll
    for (int it = 0; it < 2; it++) {
        int idx = tid + it * 512;
        int r = idx >> 4, u = idx & 15;
        pv[it] = *reinterpret_cast<const uint4*>(vt_g + (bh * CC + r) * MM + u * 8);
    }

    // ---- pass A: row sums (warp w owns row w) ----
    float cs[4], inv[4];
    #pragma unroll
    for (int s = 0; s < SS; s++)
        cs[s] = SCALE * __ldg(qsub + ((size_t)b * SS + s) * NN + n0 + warp);
    {
        float sum[4] = {0.f, 0.f, 0.f, 0.f};
        #pragma unroll
        for (int j = 0; j < 8; j++) {
            int m = j * 128 + lane * 4;
            uint2 gu = *reinterpret_cast<const uint2*>(&Gs[warp * GS_STRIDE + m]);
            float2 g01 = __half22float2(*reinterpret_cast<__half2*>(&gu.x));
            float2 g23 = __half22float2(*reinterpret_cast<__half2*>(&gu.y));
            #pragma unroll
            for (int s = 0; s < SS; s++) {
                uint2 du = *reinterpret_cast<const uint2*>(&us[s * US_STRIDE + m]);
                float2 d01 = __half22float2(*reinterpret_cast<__half2*>(&du.x));
                float2 d23 = __half22float2(*reinterpret_cast<__half2*>(&du.y));
                sum[s] += __expf(cs[s] * d01.x * g01.x) + __expf(cs[s] * d01.y * g01.y)
                        + __expf(cs[s] * d23.x * g23.x) + __expf(cs[s] * d23.y * g23.y);
            }
        }
        #pragma unroll
        for (int s = 0; s < SS; s++) {
            #pragma unroll
            for (int o = 16; o; o >>= 1)
                sum[s] += __shfl_xor_sync(0xffffffffu, sum[s], o);
            inv[s] = 1.f / sum[s];
        }
    }

    // ---- pass B: double-buffered V + Ps, one sync/chunk ----
    float accB[4][4] = {};
    const int s_own = warp >> 2;
    const int kh_ = (warp >> 1) & 1;
    const int ng = warp & 1;

    for (int mc = 0; mc < 8; mc++) {
        __half* vb = reinterpret_cast<__half*>(smem + KV_OFF + (mc & 1) * 18432);
        __half* pb = reinterpret_cast<__half*>(smem + PS_OFF + (mc & 1) * 17408);
        #pragma unroll
        for (int it = 0; it < 2; it++) {
            int idx = tid + it * 512;
            int r = idx >> 4, u = idx & 15;
            *reinterpret_cast<uint4*>(&vb[r * 136 + u * 8]) = pv[it];
        }
        {
            int m = mc * 128 + lane * 4;
            uint2 gu = *reinterpret_cast<const uint2*>(&Gs[warp * GS_STRIDE + m]);
            float2 g01 = __half22float2(*reinterpret_cast<__half2*>(&gu.x));
            float2 g23 = __half22float2(*reinterpret_cast<__half2*>(&gu.y));
            #pragma unroll
            for (int s = 0; s < SS; s++) {
                uint2 du = *reinterpret_cast<const uint2*>(&us[s * US_STRIDE + m]);
                float2 d01 = __half22float2(*reinterpret_cast<__half2*>(&du.x));
                float2 d23 = __half22float2(*reinterpret_cast<__half2*>(&du.y));
                float4 e;
                e.x = __expf(cs[s] * d01.x * g01.x) * inv[s];
                e.y = __expf(cs[s] * d01.y * g01.y) * inv[s];
                e.z = __expf(cs[s] * d23.x * g23.x) * inv[s];
                e.w = __expf(cs[s] * d23.y * g23.y) * inv[s];
                __stcs(reinterpret_cast<float4*>(
                    attn_out + ((bh * SS + s) * NN + n0 + warp) * (size_t)MM + m), e);
                __half2* pd = reinterpret_cast<__half2*>(&pb[(s * 16 + warp) * 136 + lane * 4]);
                pd[0] = __floats2half2_rn(e.x, e.y);
                pd[1] = __floats2half2_rn(e.z, e.w);
            }
        }
        if (mc < 7) {
            #pragma unroll
            for (int it = 0; it < 2; it++) {
                int idx = tid + it * 512;
                int r = idx >> 4, u = idx & 15;
                pv[it] = *reinterpret_cast<const uint4*>(
                    vt_g + (bh * CC + r) * MM + (mc + 1) * 128 + u * 8);
            }
        }
        __syncthreads();
        #pragma unroll
        for (int kt = 0; kt < 4; kt++) {
            int kk = kh_ * 4 + kt;
            unsigned af[4];
            ldsm_x4(af, pb + s_own * 16 * 136, 0, kk * 16, 136, lane);
            unsigned bf0[4], bf1[4];
            ldsm_b_x4n(bf0, vb, ng * 32, kk * 16, 136, lane);
            ldsm_b_x4n(bf1, vb, ng * 32 + 16, kk * 16, 136, lane);
            mma16816(accB[0], af, bf0);
            mma16816(accB[1], af, bf0 + 2);
            mma16816(accB[2], af, bf1);
            mma16816(accB[3], af, bf1 + 2);
        }
    }
    __syncthreads();

    // 2-way k-split reduction + hidden write (red overlays buf0)
    if (kh_ == 1) {
        #pragma unroll
        for (int nt = 0; nt < 4; nt++)
            *reinterpret_cast<float4*>(
                &red[(((s_own * 2 + ng) * 4 + nt) * 32 + lane) * 4]) =
                make_float4(accB[nt][0], accB[nt][1], accB[nt][2], accB[nt][3]);
    }
    __syncthreads();
    if (kh_ == 0) {
        #pragma unroll
        for (int nt = 0; nt < 4; nt++) {
            float4 p = *reinterpret_cast<const float4*>(
                &red[(((s_own * 2 + ng) * 4 + nt) * 32 + lane) * 4]);
            float v0 = accB[nt][0] + p.x, v1 = accB[nt][1] + p.y;
            float v2 = accB[nt][2] + p.z, v3 = accB[nt][3] + p.w;
            int r0 = lane >> 2;
            int c = ng * 32 + nt * 8 + 2 * (lane & 3);
            size_t base = ((size_t)(b * SS + s_own) * NN + n0) * DM + h * 64 + c;
            *reinterpret_cast<float2*>(&hidden_out[base + (size_t)r0 * DM]) =
                make_float2(v0, v1);
            *reinterpret_cast<float2*>(&hidden_out[base + (size_t)(r0 + 8) * DM]) =
                make_float2(v2, v3);
        }
    }
}

// =====================================================================
extern "C" void kernel_launch(void* const* d_in, const int* in_sizes, int n_in,
                              void* d_out, int out_size) {
    (void)in_sizes; (void)n_in; (void)out_size;
    const float* Xq   = (const float*)d_in[0];
    const float* Xk   = (const float*)d_in[1];
    const float* Xv   = (const float*)d_in[2];
    const float* qsub = (const float*)d_in[3];
    const float* ksub = (const float*)d_in[4];
    const float* Wq   = (const float*)d_in[5];
    const float* bq   = (const float*)d_in[6];
    const float* Wk   = (const float*)d_in[7];
    const float* bk   = (const float*)d_in[8];
    const float* Wv   = (const float*)d_in[9];
    const float* bv   = (const float*)d_in[10];

    float* out = (float*)d_out;
    float* attn_out = out + (size_t)BB * SS * NN * DM;  // hidden first, attn second

    cudaFuncSetAttribute(attn_kernel, cudaFuncAttributeMaxDynamicSharedMemorySize, K2_SMEM);

    proj_kernel<<<dim3(16, 4, 3), 512>>>(Xq, Xk, Xv, Wq, bq, Wk, bk, Wv, bv);
    attn_kernel<<<dim3(64, 8, 2), 512, K2_SMEM>>>(out, attn_out, qsub, ksub);
}

// round 17
// speedup vs baseline: 1.0489x; 1.0144x over previous
#include <cuda_runtime.h>
#include <cuda_fp16.h>

// Problem constants
#define BB 2
#define HH 8
#define NN 1024
#define MM 1024
#define SS 4
#define CC 64
#define DM 512
#define SCALE 0.125f       // 1/sqrt(64)
#define LOG2E 1.4426950408889634f

// fp16 scratch (device globals: allocation-free)
__device__ __half qh_g[(size_t)BB*HH*NN*CC];   // [bh][n][c]
__device__ __half kh_g[(size_t)BB*HH*MM*CC];   // [bh][m][c]
__device__ __half vt_g[(size_t)BB*HH*CC*MM];   // [bh][c][m]  (transposed V)

// ---------------------------------------------------------------- helpers
__device__ __forceinline__ unsigned smem_u32(const void* p) {
    return (unsigned)__cvta_generic_to_shared(p);
}

// raw ex2.approx (the MUFU op __expf uses AFTER its extra FMUL; we pre-fold log2e)
__device__ __forceinline__ float ex2f(float x) {
    float y;
    asm("ex2.approx.f32 %0, %1;" : "=f"(y) : "f"(x));
    return y;
}

__device__ __forceinline__ void ldsm_x4(unsigned r[4], const __half* base,
                                        int row, int col, int ld, int lane) {
    const __half* p = base + (size_t)(row + (lane & 7) + ((lane >> 3) & 1) * 8) * ld
                           + col + (lane >> 4) * 8;
    unsigned a = smem_u32(p);
    asm volatile("ldmatrix.sync.aligned.m8n8.x4.shared.b16 {%0,%1,%2,%3},[%4];\n"
                 : "=r"(r[0]), "=r"(r[1]), "=r"(r[2]), "=r"(r[3]) : "r"(a));
}

// B-frag pair over two n-tiles (nrow, nrow+8), same kcol
__device__ __forceinline__ void ldsm_b_x4n(unsigned r[4], const __half* base,
                                           int nrow, int kcol, int ld, int lane) {
    const __half* p = base + (size_t)(nrow + (lane & 7) + ((lane >> 4) & 1) * 8) * ld
                           + kcol + ((lane >> 3) & 1) * 8;
    unsigned a = smem_u32(p);
    asm volatile("ldmatrix.sync.aligned.m8n8.x4.shared.b16 {%0,%1,%2,%3},[%4];\n"
                 : "=r"(r[0]), "=r"(r[1]), "=r"(r[2]), "=r"(r[3]) : "r"(a));
}

// B-frag pair over two k-tiles (kcol, kcol+16), same nrow
__device__ __forceinline__ void ldsm_b_x4k(unsigned r[4], const __half* base,
                                           int nrow, int kcol, int ld, int lane) {
    const __half* p = base + (size_t)(nrow + (lane & 7)) * ld
                           + kcol + ((lane >> 3) & 1) * 8 + ((lane >> 4) & 1) * 16;
    unsigned a = smem_u32(p);
    asm volatile("ldmatrix.sync.aligned.m8n8.x4.shared.b16 {%0,%1,%2,%3},[%4];\n"
                 : "=r"(r[0]), "=r"(r[1]), "=r"(r[2]), "=r"(r[3]) : "r"(a));
}

__device__ __forceinline__ void mma16816(float c[4], const unsigned a[4], const unsigned b[2]) {
    asm volatile("mma.sync.aligned.m16n8k16.row.col.f32.f16.f16.f32 "
                 "{%0,%1,%2,%3},{%4,%5,%6,%7},{%8,%9},{%0,%1,%2,%3};\n"
                 : "+f"(c[0]), "+f"(c[1]), "+f"(c[2]), "+f"(c[3])
                 : "r"(a[0]), "r"(a[1]), "r"(a[2]), "r"(a[3]), "r"(b[0]), "r"(b[1]));
}

// =====================================================================
// Kernel 1: projections direct from fp32, 128x128 tiles (TK=64),
// double-buffered, fp32->fp16 at staging.
// grid (16, 4, 3) = 192 CTAs, 512 threads.
// =====================================================================
__global__ __launch_bounds__(512)
void proj_kernel(const float* __restrict__ Xq, const float* __restrict__ Xk,
                 const float* __restrict__ Xv,
                 const float* __restrict__ Wq, const float* __restrict__ bq,
                 const float* __restrict__ Wk, const float* __restrict__ bk,
                 const float* __restrict__ Wv, const float* __restrict__ bv) {
    const int which = blockIdx.z;
    const float* X = (which == 0) ? Xq : (which == 1) ? Xk : Xv;
    const float* W = (which == 0) ? Wq : (which == 1) ? Wk : Wv;
    const float* bias = (which == 0) ? bq : (which == 1) ? bk : bv;

    __shared__ __half As[2 * 128 * 72];   // 36864 B
    __shared__ __half Bs[2 * 128 * 72];   // 36864 B

    const int row0 = blockIdx.x * 128;
    const int j0 = blockIdx.y * 128;      // spans heads 2*by, 2*by+1
    const int tid = threadIdx.x;
    const int warp = tid >> 5, lane = tid & 31;
    const int wn = warp & 3, wc = warp >> 2;   // 4x4 warps, 32x32 per warp

    float acc[2][4][4] = {};
    float4 ra[4], rb[4];

    #pragma unroll
    for (int it = 0; it < 4; it++) {
        int idx = tid + it * 512;
        int r = idx >> 4, cf = (idx & 15) << 2;
        ra[it] = __ldg(reinterpret_cast<const float4*>(X + (size_t)(row0 + r) * DM + cf));
        rb[it] = __ldg(reinterpret_cast<const float4*>(W + (size_t)(j0 + r) * DM + cf));
    }

    for (int kc8 = 0; kc8 < 8; kc8++) {
        __half* Ab = As + (kc8 & 1) * 128 * 72;
        __half* Bb = Bs + (kc8 & 1) * 128 * 72;
        #pragma unroll
        for (int it = 0; it < 4; it++) {
            int idx = tid + it * 512;
            int r = idx >> 4, cf = (idx & 15) << 2;
            __half2* da = reinterpret_cast<__half2*>(&Ab[r * 72 + cf]);
            da[0] = __floats2half2_rn(ra[it].x, ra[it].y);
            da[1] = __floats2half2_rn(ra[it].z, ra[it].w);
            __half2* db = reinterpret_cast<__half2*>(&Bb[r * 72 + cf]);
            db[0] = __floats2half2_rn(rb[it].x, rb[it].y);
            db[1] = __floats2half2_rn(rb[it].z, rb[it].w);
        }
        __syncthreads();

        if (kc8 < 7) {
            int kc = (kc8 + 1) * 64;
            #pragma unroll
            for (int it = 0; it < 4; it++) {
                int idx = tid + it * 512;
                int r = idx >> 4, cf = (idx & 15) << 2;
                ra[it] = __ldg(reinterpret_cast<const float4*>(
                    X + (size_t)(row0 + r) * DM + kc + cf));
                rb[it] = __ldg(reinterpret_cast<const float4*>(
                    W + (size_t)(j0 + r) * DM + kc + cf));
            }
        }

        #pragma unroll
        for (int kt = 0; kt < 4; kt++) {
            unsigned af[2][4], bf0[4], bf1[4];
            #pragma unroll
            for (int mt = 0; mt < 2; mt++)
                ldsm_x4(af[mt], Ab, wn * 32 + mt * 16, kt * 16, 72, lane);
            ldsm_b_x4n(bf0, Bb, wc * 32, kt * 16, 72, lane);       // nt 0,1
            ldsm_b_x4n(bf1, Bb, wc * 32 + 16, kt * 16, 72, lane);  // nt 2,3
            #pragma unroll
            for (int mt = 0; mt < 2; mt++) {
                mma16816(acc[mt][0], af[mt], bf0);
                mma16816(acc[mt][1], af[mt], bf0 + 2);
                mma16816(acc[mt][2], af[mt], bf1);
                mma16816(acc[mt][3], af[mt], bf1 + 2);
            }
        }
        // next iter's barrier (other buffer) orders reads vs overwrite
    }

    const int h = blockIdx.y * 2 + (wc >> 1);         // warp-uniform head
    #pragma unroll
    for (int mt = 0; mt < 2; mt++) {
        int rg = row0 + wn * 32 + mt * 16 + (lane >> 2);
        #pragma unroll
        for (int nt = 0; nt < 4; nt++) {
            int j = j0 + wc * 32 + nt * 8 + 2 * (lane & 3);
            int c = j & 63;
            float b0 = __ldg(bias + j), b1 = __ldg(bias + j + 1);
            #pragma unroll
            for (int hr = 0; hr < 2; hr++) {
                int r = rg + hr * 8;
                int bi = r >> 10, seq = r & 1023;
                float v0 = acc[mt][nt][hr * 2 + 0] + b0;
                float v1 = acc[mt][nt][hr * 2 + 1] + b1;
                size_t bh = (size_t)(bi * HH + h);
                if (which == 2) {
                    vt_g[(bh * CC + c) * MM + seq]     = __float2half_rn(v0);
                    vt_g[(bh * CC + c + 1) * MM + seq] = __float2half_rn(v1);
                } else {
                    __half* dst = (which == 0) ? qh_g : kh_g;
                    *reinterpret_cast<__half2*>(&dst[(bh * NN + seq) * CC + c]) =
                        __floats2half2_rn(v0, v1);
                }
            }
        }
    }
}

// =====================================================================
// Kernel 2 (FUSED): fp16 Gs; double-buffered K / V+Ps; pass A row sums;
// pass B exp + attn + AV.  cs pre-folds log2e; raw ex2.approx.
// grid (64, 8, 2) = 1024 CTAs, 512 thr, 2 CTAs/SM.
// =====================================================================
#define GS_STRIDE 1032
#define GS_OFF   0                               // 16 x 1032 f16 = 33024
#define KV_OFF   33024                           // 2 x 18432 (K 128x72 / V 64x136)
#define PS_OFF   69888                           // 2 x 17408 ([4][16][136] f16)
#define US_OFF   104704                          // 4 x 1056 f16 = 8448
#define US_STRIDE 1056
#define K2_SMEM  113152

__global__ __launch_bounds__(512, 2)
void attn_kernel(float* __restrict__ hidden_out, float* __restrict__ attn_out,
                 const float* __restrict__ qsub, const float* __restrict__ ksub) {
    extern __shared__ char smem[];
    __half* Gs = reinterpret_cast<__half*>(smem + GS_OFF);
    __half* qs = reinterpret_cast<__half*>(smem + PS_OFF);   // overlay (pre-pass-B)
    __half* us = reinterpret_cast<__half*>(smem + US_OFF);
    float*  red = reinterpret_cast<float*>(smem + KV_OFF);   // final reduction (buf0)

    const int n0 = blockIdx.x * 16;
    const int h = blockIdx.y, b = blockIdx.z;
    const size_t bh = (size_t)b * HH + h;
    const int tid = threadIdx.x, warp = tid >> 5, lane = tid & 31;

    // prefetch K chunk 0
    uint4 pk[2];
    #pragma unroll
    for (int it = 0; it < 2; it++) {
        int idx = tid + it * 512;
        int r = idx >> 3, u = idx & 7;
        pk[it] = *reinterpret_cast<const uint4*>(kh_g + (bh * MM + r) * CC + u * 8);
    }
    // stage q tile (16 x 64 f16)
    if (tid < 128) {
        int r = tid >> 3, u = tid & 7;
        *reinterpret_cast<uint4*>(&qs[r * 72 + u * 8]) =
            *reinterpret_cast<const uint4*>(qh_g + (bh * NN + n0 + r) * CC + u * 8);
    }
    // stage ksub fp16
    #pragma unroll
    for (int it = 0; it < 2; it++) {
        int idx = tid + it * 512;
        int s = idx >> 8, mf = (idx & 255) << 2;
        float4 d = __ldg(reinterpret_cast<const float4*>(
            ksub + ((size_t)b * SS + s) * MM + mf));
        __half2* dst = reinterpret_cast<__half2*>(&us[s * US_STRIDE + mf]);
        dst[0] = __floats2half2_rn(d.x, d.y);
        dst[1] = __floats2half2_rn(d.z, d.w);
    }
    __syncthreads();

    unsigned afr[4][4];
    #pragma unroll
    for (int kt = 0; kt < 4; kt++)
        ldsm_x4(afr[kt], qs, 0, kt * 16, 72, lane);

    // ---- QK: 8 chunks of 128 m, double-buffered K, one sync/chunk ----
    for (int mc = 0; mc < 8; mc++) {
        __half* kb = reinterpret_cast<__half*>(smem + KV_OFF + (mc & 1) * 18432);
        #pragma unroll
        for (int it = 0; it < 2; it++) {
            int idx = tid + it * 512;
            int r = idx >> 3, u = idx & 7;
            *reinterpret_cast<uint4*>(&kb[r * 72 + u * 8]) = pk[it];
        }
        if (mc < 7) {
            #pragma unroll
            for (int it = 0; it < 2; it++) {
                int idx = tid + it * 512;
                int r = idx >> 3, u = idx & 7;
                pk[it] = *reinterpret_cast<const uint4*>(
                    kh_g + (bh * MM + (mc + 1) * 128 + r) * CC + u * 8);
            }
        }
        __syncthreads();
        float acc[4] = {};
        #pragma unroll
        for (int kp = 0; kp < 2; kp++) {
            unsigned bfr[4];
            ldsm_b_x4k(bfr, kb, warp * 8, kp * 32, 72, lane);
            mma16816(acc, afr[kp * 2 + 0], bfr);
            mma16816(acc, afr[kp * 2 + 1], bfr + 2);
        }
        int r = lane >> 2;
        int c0 = mc * 128 + warp * 8 + 2 * (lane & 3);
        *reinterpret_cast<__half2*>(&Gs[r * GS_STRIDE + c0]) =
            __floats2half2_rn(acc[0], acc[1]);
        *reinterpret_cast<__half2*>(&Gs[(r + 8) * GS_STRIDE + c0]) =
            __floats2half2_rn(acc[2], acc[3]);
    }
    __syncthreads();

    // prefetch V chunk 0
    uint4 pv[2];
    #pragma unroll
    for (int it = 0; it < 2; it++) {
        int idx = tid + it * 512;
        int r = idx >> 4, u = idx & 15;
        pv[it] = *reinterpret_cast<const uint4*>(vt_g + (bh * CC + r) * MM + u * 8);
    }

    // ---- pass A: row sums (warp w owns row w); cs folds log2e ----
    float cs[4], inv[4];
    #pragma unroll
    for (int s = 0; s < SS; s++)
        cs[s] = (SCALE * LOG2E) * __ldg(qsub + ((size_t)b * SS + s) * NN + n0 + warp);
    {
        float sum[4] = {0.f, 0.f, 0.f, 0.f};
        #pragma unroll
        for (int j = 0; j < 8; j++) {
            int m = j * 128 + lane * 4;
            uint2 gu = *reinterpret_cast<const uint2*>(&Gs[warp * GS_STRIDE + m]);
            float2 g01 = __half22float2(*reinterpret_cast<__half2*>(&gu.x));
            float2 g23 = __half22float2(*reinterpret_cast<__half2*>(&gu.y));
            #pragma unroll
            for (int s = 0; s < SS; s++) {
                uint2 du = *reinterpret_cast<const uint2*>(&us[s * US_STRIDE + m]);
                float2 d01 = __half22float2(*reinterpret_cast<__half2*>(&du.x));
                float2 d23 = __half22float2(*reinterpret_cast<__half2*>(&du.y));
                sum[s] += ex2f(cs[s] * d01.x * g01.x) + ex2f(cs[s] * d01.y * g01.y)
                        + ex2f(cs[s] * d23.x * g23.x) + ex2f(cs[s] * d23.y * g23.y);
            }
        }
        #pragma unroll
        for (int s = 0; s < SS; s++) {
            #pragma unroll
            for (int o = 16; o; o >>= 1)
                sum[s] += __shfl_xor_sync(0xffffffffu, sum[s], o);
            inv[s] = 1.f / sum[s];
        }
    }

    // ---- pass B: double-buffered V + Ps, one sync/chunk ----
    float accB[4][4] = {};
    const int s_own = warp >> 2;
    const int kh_ = (warp >> 1) & 1;
    const int ng = warp & 1;

    for (int mc = 0; mc < 8; mc++) {
        __half* vb = reinterpret_cast<__half*>(smem + KV_OFF + (mc & 1) * 18432);
        __half* pb = reinterpret_cast<__half*>(smem + PS_OFF + (mc & 1) * 17408);
        #pragma unroll
        for (int it = 0; it < 2; it++) {
            int idx = tid + it * 512;
            int r = idx >> 4, u = idx & 15;
            *reinterpret_cast<uint4*>(&vb[r * 136 + u * 8]) = pv[it];
        }
        {
            int m = mc * 128 + lane * 4;
            uint2 gu = *reinterpret_cast<const uint2*>(&Gs[warp * GS_STRIDE + m]);
            float2 g01 = __half22float2(*reinterpret_cast<__half2*>(&gu.x));
            float2 g23 = __half22float2(*reinterpret_cast<__half2*>(&gu.y));
            #pragma unroll
            for (int s = 0; s < SS; s++) {
                uint2 du = *reinterpret_cast<const uint2*>(&us[s * US_STRIDE + m]);
                float2 d01 = __half22float2(*reinterpret_cast<__half2*>(&du.x));
                float2 d23 = __half22float2(*reinterpret_cast<__half2*>(&du.y));
                float4 e;
                e.x = ex2f(cs[s] * d01.x * g01.x) * inv[s];
                e.y = ex2f(cs[s] * d01.y * g01.y) * inv[s];
                e.z = ex2f(cs[s] * d23.x * g23.x) * inv[s];
                e.w = ex2f(cs[s] * d23.y * g23.y) * inv[s];
                __stcs(reinterpret_cast<float4*>(
                    attn_out + ((bh * SS + s) * NN + n0 + warp) * (size_t)MM + m), e);
                __half2* pd = reinterpret_cast<__half2*>(&pb[(s * 16 + warp) * 136 + lane * 4]);
                pd[0] = __floats2half2_rn(e.x, e.y);
                pd[1] = __floats2half2_rn(e.z, e.w);
            }
        }
        if (mc < 7) {
            #pragma unroll
            for (int it = 0; it < 2; it++) {
                int idx = tid + it * 512;
                int r = idx >> 4, u = idx & 15;
                pv[it] = *reinterpret_cast<const uint4*>(
                    vt_g + (bh * CC + r) * MM + (mc + 1) * 128 + u * 8);
            }
        }
        __syncthreads();
        #pragma unroll
        for (int kt = 0; kt < 4; kt++) {
            int kk = kh_ * 4 + kt;
            unsigned af[4];
            ldsm_x4(af, pb + s_own * 16 * 136, 0, kk * 16, 136, lane);
            unsigned bf0[4], bf1[4];
            ldsm_b_x4n(bf0, vb, ng * 32, kk * 16, 136, lane);
            ldsm_b_x4n(bf1, vb, ng * 32 + 16, kk * 16, 136, lane);
            mma16816(accB[0], af, bf0);
            mma16816(accB[1], af, bf0 + 2);
            mma16816(accB[2], af, bf1);
            mma16816(accB[3], af, bf1 + 2);
        }
    }
    __syncthreads();

    // 2-way k-split reduction + hidden write (red overlays buf0)
    if (kh_ == 1) {
        #pragma unroll
        for (int nt = 0; nt < 4; nt++)
            *reinterpret_cast<float4*>(
                &red[(((s_own * 2 + ng) * 4 + nt) * 32 + lane) * 4]) =
                make_float4(accB[nt][0], accB[nt][1], accB[nt][2], accB[nt][3]);
    }
    __syncthreads();
    if (kh_ == 0) {
        #pragma unroll
        for (int nt = 0; nt < 4; nt++) {
            float4 p = *reinterpret_cast<const float4*>(
                &red[(((s_own * 2 + ng) * 4 + nt) * 32 + lane) * 4]);
            float v0 = accB[nt][0] + p.x, v1 = accB[nt][1] + p.y;
            float v2 = accB[nt][2] + p.z, v3 = accB[nt][3] + p.w;
            int r0 = lane >> 2;
            int c = ng * 32 + nt * 8 + 2 * (lane & 3);
            size_t base = ((size_t)(b * SS + s_own) * NN + n0) * DM + h * 64 + c;
            __stcs(reinterpret_cast<float2*>(&hidden_out[base + (size_t)r0 * DM]),
                   make_float2(v0, v1));
            __stcs(reinterpret_cast<float2*>(&hidden_out[base + (size_t)(r0 + 8) * DM]),
                   make_float2(v2, v3));
        }
    }
}

// =====================================================================
extern "C" void kernel_launch(void* const* d_in, const int* in_sizes, int n_in,
                              void* d_out, int out_size) {
    (void)in_sizes; (void)n_in; (void)out_size;
    const float* Xq   = (const float*)d_in[0];
    const float* Xk   = (const float*)d_in[1];
    const float* Xv   = (const float*)d_in[2];
    const float* qsub = (const float*)d_in[3];
    const float* ksub = (const float*)d_in[4];
    const float* Wq   = (const float*)d_in[5];
    const float* bq   = (const float*)d_in[6];
    const float* Wk   = (const float*)d_in[7];
    const float* bk   = (const float*)d_in[8];
    const float* Wv   = (const float*)d_in[9];
    const float* bv   = (const float*)d_in[10];

    float* out = (float*)d_out;
    float* attn_out = out + (size_t)BB * SS * NN * DM;  // hidden first, attn second

    cudaFuncSetAttribute(attn_kernel, cudaFuncAttributeMaxDynamicSharedMemorySize, K2_SMEM);

    proj_kernel<<<dim3(16, 4, 3), 512>>>(Xq, Xk, Xv, Wq, bq, Wk, bk, Wv, bv);
    attn_kernel<<<dim3(64, 8, 2), 512, K2_SMEM>>>(out, attn_out, qsub, ksub);
}